// round 8
// baseline (speedup 1.0000x reference)
#include <cuda_runtime.h>
#include <cstdint>

// YOLO loss: pred/target (bs, 7, 7, 30) f32 -> scalar f32.
// Per-WARP private cp.async.bulk pipelines: each warp owns a 3-stage ring of
// 32-cell tiles with its own mbarriers; lane 0 issues, warp waits its own
// parity, computes, recycles -- zero CTA-wide barriers in the main loop, so
// warps never stall each other. Last-block finalize.

#define S_GRID 7
#define CH 30
#define WARPS 4
#define NTHREADS (WARPS * 32)
#define STAGES 3
#define WTILE 32                              // cells per warp-tile
#define WSFLOATS (WTILE * CH)                 // 960 floats per tensor
#define WSTAGE_FLOATS (2 * WSFLOATS)          // 1920 floats (pred + targ)
#define WSTAGE_BYTES (WSTAGE_FLOATS * 4)      // 7680 B
#define WHALF_BYTES (WSFLOATS * 4)            // 3840 B
#define SMEM_BYTES (WARPS * STAGES * WSTAGE_BYTES)   // 92160 B -> 2 CTAs/SM
#define MAX_BLOCKS 296                        // 2 * 148

__device__ double g_acc = 0.0;
__device__ unsigned int g_counter = 0u;

__device__ __forceinline__ void mbar_init(uint32_t mbar, uint32_t cnt) {
    asm volatile("mbarrier.init.shared.b64 [%0], %1;" :: "r"(mbar), "r"(cnt) : "memory");
}
__device__ __forceinline__ void mbar_expect_tx(uint32_t mbar, uint32_t bytes) {
    asm volatile("mbarrier.arrive.expect_tx.shared.b64 _, [%0], %1;"
                 :: "r"(mbar), "r"(bytes) : "memory");
}
__device__ __forceinline__ void mbar_wait(uint32_t mbar, uint32_t parity) {
    asm volatile(
        "{\n\t"
        ".reg .pred P;\n\t"
        "WAIT_%=:\n\t"
        "mbarrier.try_wait.parity.acquire.cta.shared::cta.b64 P, [%0], %1, 0x989680;\n\t"
        "@P bra.uni DONE_%=;\n\t"
        "bra.uni WAIT_%=;\n\t"
        "DONE_%=:\n\t"
        "}" :: "r"(mbar), "r"(parity) : "memory");
}
__device__ __forceinline__ void bulk_g2s(uint32_t dst, const void* src,
                                         uint32_t bytes, uint32_t mbar) {
    asm volatile(
        "cp.async.bulk.shared::cta.global.mbarrier::complete_tx::bytes [%0], [%1], %2, [%3];"
        :: "r"(dst), "l"(src), "r"(bytes), "r"(mbar) : "memory");
}

// Issue one warp-tile (pred+targ halves) into a warp-private stage. Lane 0 only.
__device__ __forceinline__ void issue_wtile(uint32_t stage_base, uint32_t mbar,
                                            const char* __restrict__ pred,
                                            const char* __restrict__ targ,
                                            long long tile) {
    mbar_expect_tx(mbar, WSTAGE_BYTES);
    bulk_g2s(stage_base,               pred + tile * (long long)WHALF_BYTES, WHALF_BYTES, mbar);
    bulk_g2s(stage_base + WHALF_BYTES, targ + tile * (long long)WHALF_BYTES, WHALF_BYTES, mbar);
}

// Per-cell loss; p/t point at 30 contiguous floats (smem or gmem).
__device__ __forceinline__ float cell_loss(const float* __restrict__ p,
                                           const float* __restrict__ t)
{
    const float obj = (t[4] > 0.0f) ? 1.0f : 0.0f;

    const float dn0 = p[4] - t[4];
    const float dn1 = p[9] - t[9];
    const float noobj = dn0 * dn0 + dn1 * dn1;

    float cls = 0.0f;
    #pragma unroll
    for (int k = 10; k < 30; k++) {
        const float d = p[k] - t[k];
        cls = fmaf(d, d, cls);
    }

    const float invS = 1.0f / (float)S_GRID;
    const float tx = t[0] * invS, ty = t[1] * invS;
    const float tw = t[2], th = t[3];
    const float tx0 = tx - 0.5f * tw, tx1 = tx + 0.5f * tw;
    const float ty0 = ty - 0.5f * th, ty1 = ty + 0.5f * th;
    const float area_t = tw * th;

    float iou0 = 0.0f, iou1 = 0.0f;
    #pragma unroll
    for (int b = 0; b < 2; b++) {
        const float* q = p + 5 * b;
        const float px = q[0] * invS, py = q[1] * invS;
        const float pw = q[2], ph = q[3];
        const float lx = fmaxf(px - 0.5f * pw, tx0);
        const float rx = fminf(px + 0.5f * pw, tx1);
        const float ly = fmaxf(py - 0.5f * ph, ty0);
        const float ry = fminf(py + 0.5f * ph, ty1);
        const float wx = fmaxf(rx - lx, 0.0f);
        const float wy = fmaxf(ry - ly, 0.0f);
        const float inter = wx * wy;
        const float uni = fmaxf(pw * ph + area_t - inter, 1e-10f);
        const float iou = inter / uni;
        if (b == 0) iou0 = iou; else iou1 = iou;
    }
    // jnp.argmax picks first max -> box 1 only on strict greater.
    const int rb = (iou1 > iou0) ? 1 : 0;
    const float miou = fmaxf(iou0, iou1);

    const float* q  = p + 5 * rb;
    const float* tq = t + 5 * rb;
    const float dx = q[0] - tq[0];
    const float dy = q[1] - tq[1];
    const float lxy = dx * dx + dy * dy;
    const float dw = sqrtf(q[2]) - sqrtf(tq[2]);
    const float dh = sqrtf(q[3]) - sqrtf(tq[3]);
    const float lwh = dw * dw + dh * dh;
    const float dob = q[4] - miou;
    const float lobj = dob * dob;

    return obj * (5.0f * (lxy + lwh) + lobj + cls)
         + 0.5f * (1.0f - obj) * noobj;
}

__global__ __launch_bounds__(NTHREADS) void yolo_loss_kernel(
    const float* __restrict__ pred,
    const float* __restrict__ targ,
    int total_cells,
    float* __restrict__ out,
    double inv_bs)
{
    extern __shared__ float smem[];
    __shared__ __align__(8) uint64_t mbar_storage[WARPS * STAGES];
    __shared__ float warp_sums[WARPS];

    const int tid = threadIdx.x;
    const int wid = tid >> 5;
    const int lane = tid & 31;
    const uint32_t smem_u32 = (uint32_t)__cvta_generic_to_shared(smem);
    const uint32_t mbar_base =
        (uint32_t)__cvta_generic_to_shared(mbar_storage) + (uint32_t)(wid * STAGES) * 8u;
    const uint32_t wstage0 = smem_u32 + (uint32_t)(wid * STAGES) * WSTAGE_BYTES;
    const char* predc = (const char*)pred;
    const char* targc = (const char*)targ;

    const int ntiles = total_cells / WTILE;
    const int rem = total_cells - ntiles * WTILE;
    const long long gwarps = (long long)gridDim.x * WARPS;
    const long long w0 = (long long)blockIdx.x * WARPS + wid;

    if (tid == 0) {
        #pragma unroll
        for (int s = 0; s < WARPS * STAGES; s++)
            mbar_init((uint32_t)__cvta_generic_to_shared(mbar_storage) + 8u * s, 1u);
    }
    __syncthreads();

    // Prologue: issue this warp's tiles w0, w0+gwarps into stages 0,1.
    if (lane == 0) {
        #pragma unroll
        for (int j = 0; j < STAGES - 1; j++) {
            const long long tj = w0 + j * gwarps;
            if (tj < ntiles)
                issue_wtile(wstage0 + (uint32_t)j * WSTAGE_BYTES,
                            mbar_base + 8u * j, predc, targc, tj);
        }
    }

    float loss = 0.0f;
    unsigned int ph = 0;   // per-stage parity bitmask (warp-private)
    int s = 0;
    for (long long t = w0; t < ntiles; t += gwarps) {
        // Issue tile t+2*gwarps into the stage this warp consumed last
        // iteration (warp-local recycling; no cross-warp dependence).
        __syncwarp();
        if (lane == 0) {
            const long long tn = t + (STAGES - 1) * gwarps;
            if (tn < ntiles) {
                int sn = s + (STAGES - 1); if (sn >= STAGES) sn -= STAGES;
                issue_wtile(wstage0 + (uint32_t)sn * WSTAGE_BYTES,
                            mbar_base + 8u * sn, predc, targc, tn);
            }
        }

        // Wait for this warp's stage s.
        mbar_wait(mbar_base + 8u * s, (ph >> s) & 1u);
        ph ^= 1u << s;

        {
            const float* base = smem + (wid * STAGES + s) * WSTAGE_FLOATS;
            const float* p  = base + lane * CH;
            const float* tt = base + WSFLOATS + lane * CH;
            loss += cell_loss(p, tt);
        }

        if (++s == STAGES) s = 0;
    }

    // Tail cells (total_cells % 32; zero at bench shape), block 0 from gmem.
    if (rem && blockIdx.x == 0 && tid < rem) {
        const long long c = (long long)ntiles * WTILE + tid;
        loss += cell_loss(pred + c * CH, targ + c * CH);
    }

    // Reduction: warp -> block -> global
    #pragma unroll
    for (int o = 16; o > 0; o >>= 1)
        loss += __shfl_xor_sync(0xffffffffu, loss, o);
    if (lane == 0) warp_sums[wid] = loss;
    __syncthreads();

    if (tid == 0) {
        float bsum = 0.0f;
        #pragma unroll
        for (int w = 0; w < WARPS; w++) bsum += warp_sums[w];
        atomicAdd(&g_acc, (double)bsum);
        __threadfence();
        const unsigned int ticket = atomicAdd(&g_counter, 1u);
        if (ticket == gridDim.x - 1u) {
            const double total = atomicAdd(&g_acc, 0.0);
            out[0] = (float)(total * inv_bs);
            g_acc = 0.0;          // reset for next graph replay
            __threadfence();
            g_counter = 0u;
        }
    }
}

extern "C" void kernel_launch(void* const* d_in, const int* in_sizes, int n_in,
                              void* d_out, int out_size) {
    const float* pred = (const float*)d_in[0];
    const float* targ = (const float*)d_in[1];
    const long long n = (long long)in_sizes[0];
    const int total_cells = (int)(n / CH);            // bs * 49
    const int bs = total_cells / (S_GRID * S_GRID);
    const int nwt = total_cells / WTILE;

    int grid = MAX_BLOCKS;
    const int need = (nwt + WARPS - 1) / WARPS;
    if (grid > need) grid = need;
    if (grid < 1) grid = 1;

    cudaFuncSetAttribute(yolo_loss_kernel,
                         cudaFuncAttributeMaxDynamicSharedMemorySize, SMEM_BYTES);
    yolo_loss_kernel<<<grid, NTHREADS, SMEM_BYTES>>>(pred, targ, total_cells,
                                                     (float*)d_out,
                                                     1.0 / (double)bs);
}